// round 8
// baseline (speedup 1.0000x reference)
#include <cuda_runtime.h>
#include <cuda_fp16.h>
#include <cstdint>

// Problem constants
#define BATCH 32
#define NTOK  1024
#define FDIM  512
#define GRP   16
#define SEQ   64
#define DDIM  256
#define WIN   32
#define OCH   512
#define TOUT  993          // NTOK - WIN + 1
#define KTOT  (WIN * DDIM) // 8192
#define NEG_SLOPE 0.2f

// Scratch (device globals; no allocs allowed)
__device__ __half g_mid[BATCH * NTOK * DDIM];         // 16 MB, fp16 mid
__device__ __half g_cwT[OCH * KTOT];                  // 8 MB, conv_w transposed [O][K], fp16
__device__ float  g_part[2 * BATCH * NTOK * OCH];     // 134 MB, split-K partials

__device__ __forceinline__ unsigned f2tf(float v) {
    unsigned r;
    asm("cvt.rna.tf32.f32 %0, %1;" : "=r"(r) : "f"(v));
    return r;
}

__device__ __forceinline__ void cp16(unsigned smem, const void* g, int sz) {
    asm volatile("cp.async.ca.shared.global [%0], [%1], 16, %2;\n"
                 :: "r"(smem), "l"(g), "r"(sz));
}

__device__ __forceinline__ void ldsm4(unsigned* r, unsigned addr) {
    asm volatile("ldmatrix.sync.aligned.m8n8.x4.shared.b16 {%0,%1,%2,%3}, [%4];"
                 : "=r"(r[0]), "=r"(r[1]), "=r"(r[2]), "=r"(r[3]) : "r"(addr));
}

__device__ __forceinline__ void mma_tf32(float* c, const unsigned* a, const unsigned* b) {
    asm volatile(
        "mma.sync.aligned.m16n8k8.row.col.f32.tf32.tf32.f32 "
        "{%0,%1,%2,%3}, {%4,%5,%6,%7}, {%8,%9}, {%0,%1,%2,%3};\n"
        : "+f"(c[0]), "+f"(c[1]), "+f"(c[2]), "+f"(c[3])
        : "r"(a[0]), "r"(a[1]), "r"(a[2]), "r"(a[3]), "r"(b[0]), "r"(b[1]));
}

__device__ __forceinline__ void mma_f16(float* c, const unsigned* a, const unsigned* b) {
    asm volatile(
        "mma.sync.aligned.m16n8k16.row.col.f32.f16.f16.f32 "
        "{%0,%1,%2,%3}, {%4,%5,%6,%7}, {%8,%9}, {%0,%1,%2,%3};\n"
        : "+f"(c[0]), "+f"(c[1]), "+f"(c[2]), "+f"(c[3])
        : "r"(a[0]), "r"(a[1]), "r"(a[2]), "r"(a[3]), "r"(b[0]), "r"(b[1]));
}

// ===========================================================================
// Pre-pass: transpose conv_w [K=8192][O=512] -> g_cwT [O=512][K=8192], fp16
// ===========================================================================
__global__ __launch_bounds__(256)
void trans_cw_kernel(const float* __restrict__ cw) {
    __shared__ float tile[32][33];
    const int o0 = blockIdx.x * 32;
    const int k0 = blockIdx.y * 32;
    const int tx = threadIdx.x & 31;
    const int ty = threadIdx.x >> 5;
#pragma unroll
    for (int j = 0; j < 4; j++) {
        int k = ty + j * 8;
        tile[k][tx] = cw[(long)(k0 + k) * OCH + o0 + tx];
    }
    __syncthreads();
#pragma unroll
    for (int j = 0; j < 4; j++) {
        int o = ty + j * 8;
        g_cwT[(long)(o0 + o) * KTOT + k0 + tx] = __float2half_rn(tile[tx][o]);
    }
}

// ===========================================================================
// Kernel 1: gather + grouped GEMM via mma.sync tf32 (m16n8k8)
// CTA 128x128x16, 8 warps (4m x 2n), warp 32x64. M=2048, K=512, N=256.
// W read directly from input; tf32 rounding applied on BOTH fragment sets.
// Epilogue writes fp16 mid.
// ===========================================================================
#define BK 16
#define AST 20
#define BST 136

__global__ __launch_bounds__(256, 2)
void gemm1_mma_kernel(const float* __restrict__ x, const int* __restrict__ idx,
                      const float* __restrict__ W, const float* __restrict__ bias) {
    const int grp = blockIdx.z;
    const int m0  = blockIdx.y * 128;
    const int n0  = blockIdx.x * 128;
    const int tid  = threadIdx.x;
    const int lane = tid & 31;
    const int warp = tid >> 5;
    const int wm = warp >> 1;
    const int wn = warp & 1;
    const int gi = lane >> 2;
    const int tl = lane & 3;

    __shared__ float As[2][128][AST];
    __shared__ float Bs[2][BK][BST];
    __shared__ int   rowbase[128];

    if (tid < 128) {
        int m  = m0 + tid;
        int bb = m >> 6;
        int s  = m & 63;
        rowbase[tid] = bb * NTOK + idx[grp * SEQ + s];
    }
    __syncthreads();

    const int am0 = tid >> 2;
    const int ak0 = (tid & 3) * 4;
    const int bn0 = (tid & 31) * 4;
    const int bk0 = tid >> 5;

    const long arow0 = (long)rowbase[am0] * FDIM;
    const long arow1 = (long)rowbase[am0 + 64] * FDIM;
    const float* Bsrc = W + (long)grp * FDIM * DDIM;

    unsigned as_base = (unsigned)__cvta_generic_to_shared(&As[0][0][0]);
    unsigned bs_base = (unsigned)__cvta_generic_to_shared(&Bs[0][0][0]);
    const unsigned as_stage = 128 * AST * 4;
    const unsigned bs_stage = BK * BST * 4;

    float acc[2][8][4];
#pragma unroll
    for (int mt = 0; mt < 2; mt++)
#pragma unroll
        for (int nt = 0; nt < 8; nt++)
#pragma unroll
            for (int i = 0; i < 4; i++) acc[mt][nt][i] = 0.f;

    const int NSTAGE = FDIM / BK;   // 32

    {
        cp16(as_base + (am0 * AST + ak0) * 4, x + arow0 + ak0, 16);
        cp16(as_base + ((am0 + 64) * AST + ak0) * 4, x + arow1 + ak0, 16);
#pragma unroll
        for (int it = 0; it < 2; it++) {
            int k = bk0 + it * 8;
            cp16(bs_base + (k * BST + bn0) * 4, Bsrc + (long)k * DDIM + n0 + bn0, 16);
        }
        asm volatile("cp.async.commit_group;\n");
    }

#pragma unroll 1
    for (int s = 0; s < NSTAGE; s++) {
        asm volatile("cp.async.wait_group 0;\n");
        __syncthreads();

        if (s + 1 < NSTAGE) {
            const int ks = (s + 1) * BK;
            const unsigned ab  = as_base + ((s + 1) & 1) * as_stage;
            const unsigned bb2 = bs_base + ((s + 1) & 1) * bs_stage;
            cp16(ab + (am0 * AST + ak0) * 4, x + arow0 + ks + ak0, 16);
            cp16(ab + ((am0 + 64) * AST + ak0) * 4, x + arow1 + ks + ak0, 16);
#pragma unroll
            for (int it = 0; it < 2; it++) {
                int k = bk0 + it * 8;
                cp16(bb2 + (k * BST + bn0) * 4, Bsrc + (long)(ks + k) * DDIM + n0 + bn0, 16);
            }
            asm volatile("cp.async.commit_group;\n");
        }

        const int cur = s & 1;
#pragma unroll
        for (int kk = 0; kk < BK; kk += 8) {
            unsigned af[2][4];
#pragma unroll
            for (int mt = 0; mt < 2; mt++) {
                int rm = wm * 32 + mt * 16;
                af[mt][0] = f2tf(As[cur][rm + gi     ][kk + tl    ]);
                af[mt][1] = f2tf(As[cur][rm + gi + 8 ][kk + tl    ]);
                af[mt][2] = f2tf(As[cur][rm + gi     ][kk + tl + 4]);
                af[mt][3] = f2tf(As[cur][rm + gi + 8 ][kk + tl + 4]);
            }
            unsigned bf[8][2];
#pragma unroll
            for (int nt = 0; nt < 8; nt++) {
                int cn = wn * 64 + nt * 8;
                bf[nt][0] = f2tf(Bs[cur][kk + tl    ][cn + gi]);
                bf[nt][1] = f2tf(Bs[cur][kk + tl + 4][cn + gi]);
            }
#pragma unroll
            for (int mt = 0; mt < 2; mt++)
#pragma unroll
                for (int nt = 0; nt < 8; nt++)
                    mma_tf32(acc[mt][nt], af[mt], bf[nt]);
        }
        __syncthreads();
    }

    // epilogue: + bias, round to fp16, scatter to g_mid[b, grp*64+s, d]
#pragma unroll
    for (int mt = 0; mt < 2; mt++) {
        int r0 = m0 + wm * 32 + mt * 16 + gi;
        int r1 = r0 + 8;
#pragma unroll
        for (int nt = 0; nt < 8; nt++) {
            int c = n0 + wn * 64 + nt * 8 + 2 * tl;
            float2 bv = *(const float2*)(bias + grp * DDIM + c);
            {
                int bb = r0 >> 6, s = r0 & 63;
                __half2* dst = (__half2*)(g_mid + ((long)(bb * NTOK + grp * SEQ + s)) * DDIM + c);
                *dst = __floats2half2_rn(acc[mt][nt][0] + bv.x, acc[mt][nt][1] + bv.y);
            }
            {
                int bb = r1 >> 6, s = r1 & 63;
                __half2* dst = (__half2*)(g_mid + ((long)(bb * NTOK + grp * SEQ + s)) * DDIM + c);
                *dst = __floats2half2_rn(acc[mt][nt][2] + bv.x, acc[mt][nt][3] + bv.y);
            }
        }
    }
}

// ===========================================================================
// Kernel 2: conv1d implicit GEMM, fp16 m16n8k16, SPLIT-K = 2.
//   Each CTA: 128x128 tile, K range [kh*4096, kh*4096+4096) = 64 stages of 64.
//   Writes fp32 partials to g_part (no bias/relu). grid z = b*2 + kh.
// ===========================================================================
#define BKH 64                       // k-halves per stage
#define KSPLIT 4096                  // k-halves per CTA
#define TILE_B 16384                 // 128 * 64 * 2 bytes
#define SM_A 0
#define SM_B (3 * TILE_B)
#define SM_TOTAL_CONV (6 * TILE_B)   // 96 KB

__global__ __launch_bounds__(128, 2)
void conv_mma_kernel() {
    extern __shared__ __align__(128) char smem[];
    unsigned smem_base;
    asm("{ .reg .u64 t; cvta.to.shared.u64 t, %1; cvt.u32.u64 %0, t; }"
        : "=r"(smem_base) : "l"(smem));

    const int bz = blockIdx.z;
    const int b  = bz >> 1;
    const int kh = bz & 1;
    const int t0 = blockIdx.y * 128;
    const int n0 = blockIdx.x * 128;
    const int tid  = threadIdx.x;
    const int lane = tid & 31;
    const int warp = tid >> 5;
    const int wm = warp >> 1;        // 0..1 -> m offset wm*64
    const int wn = warp & 1;         // 0..1 -> n offset wn*64
    const int gi = lane >> 2;
    const int tl = lane & 3;
    const int grp8 = lane >> 3;      // 0..3
    const int r8   = lane & 7;

    const __half* midb = g_mid + (long)b * NTOK * DDIM;
    const int kbase = kh * KSPLIT;

    float acc[4][8][4];
#pragma unroll
    for (int mt = 0; mt < 4; mt++)
#pragma unroll
        for (int nt = 0; nt < 8; nt++)
#pragma unroll
            for (int i = 0; i < 4; i++) acc[mt][nt][i] = 0.f;

    const int NS = KSPLIT / BKH;   // 64

    auto load_stage = [&](int it) {
        const int ks = kbase + it * BKH; // global k offset in halves
        const int w  = ks >> 8;          // window position
        const int d0 = ks & 255;         // d offset in halves
        const int buf = it % 3;
        const unsigned abase = smem_base + SM_A + buf * TILE_B;
        const unsigned bbase = smem_base + SM_B + buf * TILE_B;
#pragma unroll
        for (int i = 0; i < 8; i++) {
            int c   = tid + i * 128;     // 0..1023
            int row = c >> 3;
            int ch  = c & 7;             // 16B chunk = 8 halves
            int t   = t0 + row + w;
            cp16(abase + row * 128 + ((ch ^ (row & 7)) * 16),
                 midb + (long)t * DDIM + d0 + ch * 8, (t < NTOK) ? 16 : 0);
        }
#pragma unroll
        for (int i = 0; i < 8; i++) {
            int c   = tid + i * 128;
            int row = c >> 3;
            int ch  = c & 7;
            cp16(bbase + row * 128 + ((ch ^ (row & 7)) * 16),
                 g_cwT + (long)(n0 + row) * KTOT + ks + ch * 8, 16);
        }
        asm volatile("cp.async.commit_group;\n");
    };

    auto ldfrag = [&](unsigned af[4][4], unsigned bf[4][4],
                      int kc, unsigned abase, unsigned bbase) {
#pragma unroll
        for (int mt = 0; mt < 4; mt++) {
            int row = wm * 64 + mt * 16 + (grp8 & 1) * 8 + r8;
            int ch  = kc + (grp8 >> 1);
            ldsm4(af[mt], abase + row * 128 + ((ch ^ (row & 7)) * 16));
        }
#pragma unroll
        for (int q = 0; q < 4; q++) {
            int row = wn * 64 + q * 16 + (grp8 >> 1) * 8 + r8;
            int ch  = kc + (grp8 & 1);
            ldsm4(bf[q], bbase + row * 128 + ((ch ^ (row & 7)) * 16));
        }
    };

    load_stage(0);
    load_stage(1);

    unsigned af[2][4][4];
    unsigned bf[2][4][4];

#pragma unroll 1
    for (int s = 0; s < NS; s++) {
        if (s + 1 < NS) asm volatile("cp.async.wait_group 1;\n");
        else            asm volatile("cp.async.wait_group 0;\n");
        __syncthreads();

        if (s + 2 < NS) load_stage(s + 2);

        const int buf = s % 3;
        const unsigned abase = smem_base + SM_A + buf * TILE_B;
        const unsigned bbase = smem_base + SM_B + buf * TILE_B;

        ldfrag(af[0], bf[0], 0, abase, bbase);

#pragma unroll
        for (int k4 = 0; k4 < 4; k4++) {          // 4 k16 slices per stage
            const int cur = k4 & 1;
            if (k4 < 3)
                ldfrag(af[cur ^ 1], bf[cur ^ 1], (k4 + 1) * 2, abase, bbase);
#pragma unroll
            for (int mt = 0; mt < 4; mt++)
#pragma unroll
                for (int nt = 0; nt < 8; nt++)
                    mma_f16(acc[mt][nt], af[cur][mt], &bf[cur][nt >> 1][(nt & 1) * 2]);
        }
    }

    // epilogue: raw fp32 partials (bias/relu live in the reduce kernel)
    float* pbase = g_part + (long)(kh * BATCH + b) * NTOK * OCH;
#pragma unroll
    for (int mt = 0; mt < 4; mt++) {
        int r0 = t0 + wm * 64 + mt * 16 + gi;
        int r1 = r0 + 8;
#pragma unroll
        for (int nt = 0; nt < 8; nt++) {
            int c = n0 + wn * 64 + nt * 8 + 2 * tl;
            *(float2*)(pbase + (long)r0 * OCH + c) = make_float2(acc[mt][nt][0], acc[mt][nt][1]);
            *(float2*)(pbase + (long)r1 * OCH + c) = make_float2(acc[mt][nt][2], acc[mt][nt][3]);
        }
    }
}

// ===========================================================================
// Kernel 3: split-K reduce + bias + leaky relu.  grid (TOUT, BATCH), block 128.
// ===========================================================================
__global__ __launch_bounds__(128)
void reduce_kernel(const float* __restrict__ cb, float* __restrict__ y) {
    const int t = blockIdx.x;
    const int b = blockIdx.y;
    const int o = threadIdx.x * 4;

    const float* p0 = g_part + ((long)b * NTOK + t) * OCH + o;
    const float* p1 = g_part + ((long)(BATCH + b) * NTOK + t) * OCH + o;
    float4 a  = *(const float4*)p0;
    float4 c4 = *(const float4*)p1;
    float4 bv = *(const float4*)(cb + o);
    float4 v;
    v.x = a.x + c4.x + bv.x;
    v.y = a.y + c4.y + bv.y;
    v.z = a.z + c4.z + bv.z;
    v.w = a.w + c4.w + bv.w;
    v.x = (v.x >= 0.f) ? v.x : NEG_SLOPE * v.x;
    v.y = (v.y >= 0.f) ? v.y : NEG_SLOPE * v.y;
    v.z = (v.z >= 0.f) ? v.z : NEG_SLOPE * v.z;
    v.w = (v.w >= 0.f) ? v.w : NEG_SLOPE * v.w;
    *(float4*)(y + ((long)b * TOUT + t) * OCH + o) = v;
}

// ===========================================================================
extern "C" void kernel_launch(void* const* d_in, const int* in_sizes, int n_in,
                              void* d_out, int out_size) {
    const float* x    = (const float*)d_in[0];
    const int*   idx  = (const int*)  d_in[1];
    const float* W    = (const float*)d_in[2];
    const float* bias = (const float*)d_in[3];
    const float* cw   = (const float*)d_in[4];
    const float* cb   = (const float*)d_in[5];
    float* y = (float*)d_out;

    cudaFuncSetAttribute(conv_mma_kernel,
                         cudaFuncAttributeMaxDynamicSharedMemorySize, SM_TOTAL_CONV);

    trans_cw_kernel<<<dim3(OCH / 32, KTOT / 32), 256>>>(cw);

    dim3 grid1(DDIM / 128, (BATCH * SEQ) / 128, GRP);   // (2, 16, 16)
    gemm1_mma_kernel<<<grid1, 256>>>(x, idx, W, bias);

    dim3 grid2(OCH / 128, NTOK / 128, BATCH * 2);       // (4, 8, 64) split-K
    conv_mma_kernel<<<grid2, 128, SM_TOTAL_CONV>>>();

    reduce_kernel<<<dim3(TOUT, BATCH), 128>>>(cb, y);
}